// round 17
// baseline (speedup 1.0000x reference)
#include <cuda_runtime.h>
#include <cstdint>
#include <cstddef>

#define BB 2
#define HH 16
#define SEQ 2048
#define HD 128
#define TQ 128           // q rows per block
#define TKK 64           // k positions per chunk
#define NCH (SEQ / TKK)  // 32
#define SCALE 0.08838834764831845f

#define STR 132   // stride (floats) Q/K tiles
#define PSTR 68   // stride (floats) P tile
#define VSTR 136  // stride (floats) V tile

// fused smem map (floats)
#define O_Q   0                    // [128][132] -> 16896
#define O_K   16896                // [64][132]  -> 25344
#define O_V0  25344                // [64][136]  -> 34048
#define O_V1  34048                // [64][136]  -> 42752
#define O_P   42752                // [128][68]  -> 51456
#define O_MM  51456                // [128] running max
#define O_LL  51584                // [128] running sum
#define O_IL  51712                // [128] 1/sum
#define O_SCL 51840                // [128] out-acc rescale
#define O_PMX 51968                // [2][128] partial max -> reused as W after merge
#define O_PSM 52224                // [2][128] partial sum
#define SMEM_F 52480
#define SMEMB (SMEM_F * 4)         // 209920 B -> 1 CTA/SM

#define NMW (BB * SEQ * (SEQ / 32))   // mask words: 262144

__device__ float g_kT[(size_t)BB * HH * SEQ * HD];
__device__ float g_vT[(size_t)BB * HH * SEQ * HD];
__device__ float g_rm[(size_t)BB * HH * 16 * NCH * 256];
__device__ float g_mf[BB * HH * SEQ];
__device__ float g_il[BB * HH * SEQ];
__device__ uint32_t g_mk[NMW];

__device__ __forceinline__ uint32_t smem_u32(const void* p) {
    uint32_t a;
    asm("{ .reg .u64 t; cvta.to.shared.u64 t, %1; cvt.u32.u64 %0, t; }"
        : "=r"(a) : "l"(p));
    return a;
}
__device__ __forceinline__ float tf32r(float x) {
    uint32_t u; asm("cvt.rna.tf32.f32 %0, %1;" : "=r"(u) : "f"(x));
    return __uint_as_float(u);
}
__device__ __forceinline__ float4 t4(float4 v) {
    return make_float4(tf32r(v.x), tf32r(v.y), tf32r(v.z), tf32r(v.w));
}
// fast exp on fma/alu pipes, |rel err| ~1e-6 for x <= 0
__device__ __forceinline__ float fexp(float x) {
    x = fmaxf(x, -87.0f);
    float y = x * 1.442695041f;
    float t = y + 12582912.0f;
    int   n = __float_as_int(t) - 0x4B400000;
    float f = y - (t - 12582912.0f);
    float p = 1.33335581e-3f;
    p = fmaf(p, f, 9.61812910e-3f);
    p = fmaf(p, f, 5.55041087e-2f);
    p = fmaf(p, f, 2.40226507e-1f);
    p = fmaf(p, f, 6.93147182e-1f);
    p = fmaf(p, f, 1.0f);
    return p * __int_as_float((n + 127) << 23);
}
__device__ __forceinline__ void mma8(float* c, const uint32_t* a, uint32_t b0, uint32_t b1) {
    asm volatile(
        "mma.sync.aligned.m16n8k8.row.col.f32.tf32.tf32.f32 "
        "{%0,%1,%2,%3}, {%4,%5,%6,%7}, {%8,%9}, {%0,%1,%2,%3};"
        : "+f"(c[0]), "+f"(c[1]), "+f"(c[2]), "+f"(c[3])
        : "r"(a[0]), "r"(a[1]), "r"(a[2]), "r"(a[3]), "r"(b0), "r"(b1));
}
#define CP16(dst, src) \
    asm volatile("cp.async.cg.shared.global [%0], [%1], 16;" :: "r"(dst), "l"(src))
#define CP_COMMIT asm volatile("cp.async.commit_group;" ::: "memory")
#define CP_WAIT0 asm volatile("cp.async.wait_group 0;" ::: "memory")

// k_prep: tf32-round K and V; pack mask into bits.
__global__ __launch_bounds__(512) void k_prep(const float4* __restrict__ ksrc,
                                              const float4* __restrict__ vsrc,
                                              const int* __restrict__ msrc,
                                              float4* __restrict__ kdst,
                                              float4* __restrict__ vdst, int n4) {
    int i = blockIdx.x * 512 + threadIdx.x;
    if (i < n4) {
        kdst[i] = t4(ksrc[i]);
    } else if (i < 2 * n4) {
        vdst[i - n4] = t4(vsrc[i - n4]);
    } else if (i < 2 * n4 + NMW) {
        int j = i - 2 * n4;
        const int4* mp = (const int4*)(msrc + (size_t)j * 32);
        uint32_t bits = 0;
        #pragma unroll
        for (int p = 0; p < 8; p++) {
            int4 m4 = mp[p];
            bits |= (uint32_t)(m4.x != 0) << (4 * p);
            bits |= (uint32_t)(m4.y != 0) << (4 * p + 1);
            bits |= (uint32_t)(m4.z != 0) << (4 * p + 2);
            bits |= (uint32_t)(m4.w != 0) << (4 * p + 3);
        }
        g_mk[j] = bits;
    }
}

// ---------------------------------------------------------------------------
// Flash-fused: scores + online softmax + out = P@V in one pass.
// grid (16 qt, 32 bh), 512 thr (16 warps), 1 CTA/SM.
// Writes e=exp(s-rm) to attn buffer (normalized later by k_norm) and out.
// ---------------------------------------------------------------------------
__global__ __launch_bounds__(512, 1) void k_fused(
    const float* __restrict__ q,
    const float* __restrict__ bias, float* __restrict__ attn,
    float* __restrict__ out) {
    extern __shared__ float S[];
    uint32_t* SU = (uint32_t*)S;
    const uint32_t smb = smem_u32(S);
    const int tid = threadIdx.x, w = tid >> 5, lane = tid & 31;
    const int qt = blockIdx.x, bh = blockIdx.y, b = bh >> 4, h = bh & 15;
    const int mg = w >> 1, ng = w & 1;        // score layout: 8M x 2N, tile 16x32
    const int omg = w >> 2, ong = w & 3;      // PV layout: 4M x 4N, tile 32x32
    const int lg = lane >> 2, lm = lane & 3;

    const float* qb = q + ((size_t)bh * SEQ + (size_t)qt * TQ) * HD;
    const float* kb = g_kT + (size_t)bh * SEQ * HD;
    const float* vb = g_vT + (size_t)bh * SEQ * HD;
    float* ab = attn + ((size_t)bh * SEQ + (size_t)qt * TQ) * SEQ;
    const float* bb = bias + ((size_t)h * SEQ + (size_t)qt * TQ) * SEQ;
    const uint32_t* mkb = g_mk + ((size_t)b * SEQ + (size_t)qt * TQ) * (SEQ / 32);
    float* ob = out + ((size_t)bh * SEQ + (size_t)qt * TQ) * HD;
    const size_t grmb = (size_t)(bh * 16 + qt) * (NCH * 256);

    // stage Q (pre-scaled, tf32)
    #pragma unroll
    for (int p = 0; p < 8; p++) {
        int idx = p * 2048 + tid * 4;
        int r = idx >> 7, c = idx & 127;
        float4 qv = *(const float4*)(qb + idx);
        qv.x *= SCALE; qv.y *= SCALE; qv.z *= SCALE; qv.w *= SCALE;
        *(float4*)(S + O_Q + r * STR + c) = t4(qv);
    }
    if (tid < 128) { S[O_MM + tid] = -3.0e38f; S[O_LL + tid] = 0.0f; }
    // K(0) + V(0)
    #pragma unroll
    for (int p = 0; p < 4; p++) {
        int idx = p * 2048 + tid * 4;
        int r = idx >> 7, c = idx & 127;
        CP16(smb + (uint32_t)(O_K + r * STR + c) * 4u, kb + idx);
        CP16(smb + (uint32_t)(O_V0 + r * VSTR + c) * 4u, vb + idx);
    }
    CP_COMMIT;

    float acc2[2][4][4];   // out accumulator 32x32 warp tile
    #pragma unroll
    for (int mt = 0; mt < 2; mt++)
        #pragma unroll
        for (int nt = 0; nt < 4; nt++)
            #pragma unroll
            for (int j = 0; j < 4; j++) acc2[mt][nt][j] = 0.0f;

    for (int i = 0; i < NCH; i++) {
        CP_WAIT0;
        __syncthreads();           // K(i), V(i) visible; P free (PV(i-1) done)
        if (i < NCH - 1) {         // V(i+1) into other buffer
            const float* vc = vb + (size_t)(i + 1) * TKK * HD;
            const uint32_t vbn = O_V0 + (uint32_t)(((i + 1) & 1) * (O_V1 - O_V0));
            #pragma unroll
            for (int p = 0; p < 4; p++) {
                int idx = p * 2048 + tid * 4;
                int r = idx >> 7, c = idx & 127;
                CP16(smb + (vbn + r * VSTR + c) * 4u, vc + idx);
            }
            CP_COMMIT;
        }

        // ---- score MMA: 16x32 warp tile ----
        float acc[4][4];
        #pragma unroll
        for (int nt = 0; nt < 4; nt++)
            #pragma unroll
            for (int j = 0; j < 4; j++) acc[nt][j] = 0.0f;
        #pragma unroll 4
        for (int ks = 0; ks < 16; ks++) {
            const int kc = ks * 8;
            uint32_t a[4];
            const int r0 = mg * 16 + lg;
            a[0] = SU[O_Q + r0 * STR + kc + lm];
            a[1] = SU[O_Q + (r0 + 8) * STR + kc + lm];
            a[2] = SU[O_Q + r0 * STR + kc + lm + 4];
            a[3] = SU[O_Q + (r0 + 8) * STR + kc + lm + 4];
            #pragma unroll
            for (int nt = 0; nt < 4; nt++) {
                int nr = ng * 32 + nt * 8 + lg;
                uint32_t b0 = SU[O_K + nr * STR + kc + lm];
                uint32_t b1 = SU[O_K + nr * STR + kc + lm + 4];
                mma8(acc[nt], a, b0, b1);
            }
        }

        // ---- epilogue: bias+mask bits, rm, e=exp(s-rm), write e, partials ----
        float ev[2][8];
        #pragma unroll
        for (int hh = 0; hh < 2; hh++) {
            int r = mg * 16 + hh * 8 + lg;
            const size_t rb = (size_t)r * SEQ + (size_t)i * TKK + ng * 32 + 2 * lm;
            const uint32_t mw = mkb[(size_t)r * (SEQ / 32) + i * 2 + ng];
            float rm = -3.0e38f;
            #pragma unroll
            for (int nt = 0; nt < 4; nt++) {
                float2 bv = *(const float2*)(bb + rb + nt * 8);
                float s0 = acc[nt][2 * hh] + bv.x;
                float s1 = acc[nt][2 * hh + 1] + bv.y;
                if (!((mw >> (nt * 8 + 2 * lm)) & 1u)) s0 = -1.0e9f;
                if (!((mw >> (nt * 8 + 2 * lm + 1)) & 1u)) s1 = -1.0e9f;
                ev[hh][2 * nt] = s0; ev[hh][2 * nt + 1] = s1;
                rm = fmaxf(rm, fmaxf(s0, s1));
            }
            rm = fmaxf(rm, __shfl_xor_sync(0xffffffffu, rm, 1));
            rm = fmaxf(rm, __shfl_xor_sync(0xffffffffu, rm, 2));
            float e = 0.0f;
            #pragma unroll
            for (int j = 0; j < 8; j++) { ev[hh][j] = fexp(ev[hh][j] - rm); e += ev[hh][j]; }
            #pragma unroll
            for (int nt = 0; nt < 4; nt++)
                *(float2*)(ab + rb + nt * 8) =
                    make_float2(ev[hh][2 * nt], ev[hh][2 * nt + 1]);
            e += __shfl_xor_sync(0xffffffffu, e, 1);
            e += __shfl_xor_sync(0xffffffffu, e, 2);
            if (lm == 0) {
                S[O_PMX + ng * 128 + r] = rm;
                S[O_PSM + ng * 128 + r] = e;
                g_rm[grmb + (size_t)i * 256 + ng * 128 + r] = rm;
            }
        }
        __syncthreads();           // partials visible; all past score MMA
        if (i < NCH - 1) {         // K(i+1) into single K buffer
            const float* kc2 = kb + (size_t)(i + 1) * TKK * HD;
            #pragma unroll
            for (int p = 0; p < 4; p++) {
                int idx = p * 2048 + tid * 4;
                int r = idx >> 7, c = idx & 127;
                CP16(smb + (uint32_t)(O_K + r * STR + c) * 4u, kc2 + idx);
            }
            CP_COMMIT;
        }

        // ---- merge stats; compute SCL and W (into PMX slots) ----
        if (tid < 128) {
            int r = tid;
            float m0 = S[O_PMX + r], m1 = S[O_PMX + 128 + r];
            float mo = S[O_MM + r];
            float mn = fmaxf(mo, fmaxf(m0, m1));
            float scl = fexp(mo - mn);
            float w0 = fexp(m0 - mn), w1 = fexp(m1 - mn);
            S[O_LL + r] = S[O_LL + r] * scl +
                          S[O_PSM + r] * w0 + S[O_PSM + 128 + r] * w1;
            S[O_MM + r] = mn;
            S[O_SCL + r] = scl;
            S[O_PMX + r] = w0;
            S[O_PMX + 128 + r] = w1;
        }
        __syncthreads();           // merge visible

        // ---- stage p = e*W into P tile; rescale out acc by SCL ----
        #pragma unroll
        for (int hh = 0; hh < 2; hh++) {
            int r = mg * 16 + hh * 8 + lg;
            float wsc = S[O_PMX + ng * 128 + r];
            #pragma unroll
            for (int nt = 0; nt < 4; nt++) {
                int c = ng * 32 + nt * 8 + 2 * lm;
                float p0 = tf32r(ev[hh][2 * nt] * wsc);
                float p1 = tf32r(ev[hh][2 * nt + 1] * wsc);
                *(float2*)(S + O_P + r * PSTR + c) = make_float2(p0, p1);
            }
        }
        #pragma unroll
        for (int mt = 0; mt < 2; mt++)
            #pragma unroll
            for (int hh = 0; hh < 2; hh++) {
                int r = omg * 32 + mt * 16 + hh * 8 + lg;
                float scl = S[O_SCL + r];
                #pragma unroll
                for (int nt = 0; nt < 4; nt++) {
                    acc2[mt][nt][2 * hh] *= scl;
                    acc2[mt][nt][2 * hh + 1] *= scl;
                }
            }
        __syncthreads();           // P staged

        // ---- PV MMA: out += P(i) @ V(i), warp tile 32x32 ----
        const uint32_t vbase = O_V0 + (uint32_t)((i & 1) * (O_V1 - O_V0));
        #pragma unroll 2
        for (int ks = 0; ks < 8; ks++) {
            const int kc = ks * 8;
            uint32_t a[2][4];
            #pragma unroll
            for (int mt = 0; mt < 2; mt++) {
                int r0 = omg * 32 + mt * 16 + lg;
                a[mt][0] = SU[O_P + r0 * PSTR + kc + lm];
                a[mt][1] = SU[O_P + (r0 + 8) * PSTR + kc + lm];
                a[mt][2] = SU[O_P + r0 * PSTR + kc + lm + 4];
                a[mt][3] = SU[O_P + (r0 + 8) * PSTR + kc + lm + 4];
            }
            #pragma unroll
            for (int nt = 0; nt < 4; nt++) {
                int nc = ong * 32 + nt * 8 + lg;
                uint32_t b0 = SU[vbase + (kc + lm) * VSTR + nc];
                uint32_t b1 = SU[vbase + (kc + lm + 4) * VSTR + nc];
                mma8(acc2[0][nt], a[0], b0, b1);
                mma8(acc2[1][nt], a[1], b0, b1);
            }
        }
    }

    __syncthreads();
    if (tid < 128) {               // finalize stats for k_norm + out scaling
        float il = 1.0f / S[O_LL + tid];
        S[O_IL + tid] = il;
        size_t g = (size_t)bh * SEQ + (size_t)qt * TQ + tid;
        g_mf[g] = S[O_MM + tid];
        g_il[g] = il;
    }
    __syncthreads();

    // out = acc / l
    #pragma unroll
    for (int mt = 0; mt < 2; mt++)
        #pragma unroll
        for (int hh = 0; hh < 2; hh++) {
            int r = omg * 32 + mt * 16 + hh * 8 + lg;
            float il = S[O_IL + r];
            #pragma unroll
            for (int nt = 0; nt < 4; nt++) {
                int col = ong * 32 + nt * 8 + 2 * lm;
                *(float2*)(ob + (size_t)r * HD + col) =
                    make_float2(acc2[mt][nt][2 * hh] * il,
                                acc2[mt][nt][2 * hh + 1] * il);
            }
        }
}

// ---------------------------------------------------------------------------
// k_norm: attn = e * exp(rm - m_fin) / l, in place. Streaming, full occupancy.
// grid: BB*HH*SEQ/8 blocks of 256 (8 rows per block, 32 lanes per row).
// ---------------------------------------------------------------------------
__global__ __launch_bounds__(256) void k_norm(float* __restrict__ attn) {
    const int tid = threadIdx.x, lane = tid & 31, rloc = tid >> 5;
    const size_t g = (size_t)blockIdx.x * 8 + rloc;
    const int bh = (int)(g >> 11);
    const int rs = (int)(g & 2047);
    const int qt = rs >> 7, r128 = rs & 127;
    const float mf = g_mf[g], il = g_il[g];
    const float* rmb = g_rm + (size_t)(bh * 16 + qt) * (NCH * 256);
    float* row = attn + g * SEQ;
    #pragma unroll
    for (int j = 0; j < 16; j++) {
        int c = j * 128 + lane * 4;
        int chunk = c >> 6, ng = (c >> 5) & 1;
        float fac = fexp(rmb[chunk * 256 + ng * 128 + r128] - mf) * il;
        float4 e4 = *(float4*)(row + c);
        e4.x *= fac; e4.y *= fac; e4.z *= fac; e4.w *= fac;
        *(float4*)(row + c) = e4;
    }
}

extern "C" void kernel_launch(void* const* d_in, const int* in_sizes, int n_in,
                              void* d_out, int out_size) {
    const float* q    = (const float*)d_in[0];
    const float* k    = (const float*)d_in[1];
    const float* v    = (const float*)d_in[2];
    const int*   mask = (const int*)d_in[3];
    const float* bias = (const float*)d_in[4];

    float* out  = (float*)d_out;
    float* attn = out + (size_t)BB * HH * SEQ * HD;

    float* kT; cudaGetSymbolAddress((void**)&kT, g_kT);
    float* vT; cudaGetSymbolAddress((void**)&vT, g_vT);

    cudaFuncSetAttribute(k_fused, cudaFuncAttributeMaxDynamicSharedMemorySize, SMEMB);

    const int n4 = (BB * HH * SEQ * HD) / 4;
    const int total = 2 * n4 + NMW;
    k_prep<<<(total + 511) / 512, 512>>>((const float4*)k, (const float4*)v, mask,
                                         (float4*)kT, (float4*)vT, n4);

    dim3 grid(SEQ / TQ, BB * HH);
    k_fused<<<grid, 512, SMEMB>>>(q, bias, attn, out);

    k_norm<<<(BB * HH * SEQ) / 8, 256>>>(attn);
}